// round 3
// baseline (speedup 1.0000x reference)
#include <cuda_runtime.h>

#define H    16
#define NBOX 128
#define DIN  256
#define DKD  128
#define DG   64

typedef unsigned long long ull;

// Scratch (device globals — no allocations allowed)
__device__ float g_glog[H * NBOX * NBOX];      // log(clip(relu(gate))): 1 MB
__device__ float g_qkv[3 * H * NBOX * DKD];    // k,q,v projections: 3 MB
__device__ float g_partial[H * 4 * DKD];       // per-mtile partial colsums

// ---- packed f32x2 helpers (sm_10x FFMA2) ----------------------------------
__device__ __forceinline__ void fma2(ull& acc, ull a, ull b) {
    asm("fma.rn.f32x2 %0, %1, %2, %0;" : "+l"(acc) : "l"(a), "l"(b));
}
__device__ __forceinline__ ull dup2(float a) {
    ull r; asm("mov.b64 %0, {%1, %1};" : "=l"(r) : "f"(a)); return r;
}
__device__ __forceinline__ float2 unpack2(ull v) {
    float2 r; asm("mov.b64 {%0, %1}, %2;" : "=f"(r.x), "=f"(r.y) : "l"(v)); return r;
}

// ---------------------------------------------------------------------------
// k_front: fused gate + projections.
//   blocks [0,192):   proj tile: C(32x128) = f_a(32x256) @ W[h](256x128) + b
//                     mapping: tr=tid&15 -> rows {2tr,2tr+1}; tc=tid>>4 -> cols 8tc..8tc+7
//                     (warps hold only 2 distinct tc -> B loads broadcast, 1cyc)
//   blocks [192,448): gate: glog[h,m,n] = log(max(pos[m,n,:]·WG[h]+bg[h],1e-6))
// ---------------------------------------------------------------------------
__global__ void __launch_bounds__(256) k_front(
        const float* __restrict__ f_a,
        const float* __restrict__ pos,
        const float* __restrict__ WG, const float* __restrict__ bg,
        const float* __restrict__ WK, const float* __restrict__ bk,
        const float* __restrict__ WQ, const float* __restrict__ bq,
        const float* __restrict__ WV, const float* __restrict__ bv) {
    __shared__ __align__(16) char smem_raw[25600];
    int tid = threadIdx.x;

    if (blockIdx.x < 192) {
        // ---------------- proj path ----------------
        // As2T[d][r]: dup'd A transposed (32 d x 34 pad) : 8704 B
        // Bs2[d][j] : B cols as f32x2 pairs (32 d x 66 pad): 16896 B
        ull (*As2T)[34] = (ull(*)[34])smem_raw;
        ull (*Bs2)[66]  = (ull(*)[66])(smem_raw + 32 * 34 * 8);

        int bid = blockIdx.x;
        int mt = bid & 3;
        int p  = (bid >> 2) % 3;
        int h  = bid / 12;
        const float* W  = (p == 0) ? WK : ((p == 1) ? WQ : WV);
        const float* bb = (p == 0) ? bk : ((p == 1) ? bq : bv);

        int m0 = mt * 32;
        int tr = tid & 15;      // rows 2tr, 2tr+1
        int tc = tid >> 4;      // cols 8tc .. 8tc+7
        int r0 = 2 * tr;

        ull acc[2][4] = {};

        for (int kk = 0; kk < DIN; kk += 32) {
            // A fill: 32x32 chunk -> transposed + f32x2-duplicated
            {
                int r = tid >> 3, c4 = tid & 7;
                float4 v = *(const float4*)&f_a[(m0 + r) * DIN + kk + 4 * c4];
                As2T[4 * c4 + 0][r] = dup2(v.x);
                As2T[4 * c4 + 1][r] = dup2(v.y);
                As2T[4 * c4 + 2][r] = dup2(v.z);
                As2T[4 * c4 + 3][r] = dup2(v.w);
            }
            // B fill: 32x128 chunk of W[h]
#pragma unroll
            for (int it = 0; it < 4; ++it) {
                int fidx = tid + 256 * it;
                int d = fidx >> 5, k4 = fidx & 31;
                float4 v = *(const float4*)&W[((long)h * DIN + kk + d) * DKD + 4 * k4];
                *(float4*)&Bs2[d][2 * k4] = v;
            }
            __syncthreads();

#pragma unroll
            for (int d0 = 0; d0 < 32; d0 += 4) {
                // register-cache A for 4 d: one LDS.128 per d (both rows, dup'd)
                ulonglong2 a4[4];
#pragma unroll
                for (int dd = 0; dd < 4; ++dd)
                    a4[dd] = *(ulonglong2*)&As2T[d0 + dd][r0];
#pragma unroll
                for (int dd = 0; dd < 4; ++dd) {
                    ulonglong2 b0 = *(ulonglong2*)&Bs2[d0 + dd][4 * tc];
                    ulonglong2 b1 = *(ulonglong2*)&Bs2[d0 + dd][4 * tc + 2];
                    fma2(acc[0][0], a4[dd].x, b0.x);
                    fma2(acc[0][1], a4[dd].x, b0.y);
                    fma2(acc[0][2], a4[dd].x, b1.x);
                    fma2(acc[0][3], a4[dd].x, b1.y);
                    fma2(acc[1][0], a4[dd].y, b0.x);
                    fma2(acc[1][1], a4[dd].y, b0.y);
                    fma2(acc[1][2], a4[dd].y, b1.x);
                    fma2(acc[1][3], a4[dd].y, b1.y);
                }
            }
            __syncthreads();
        }

        float* outp = g_qkv + (long)(p * H + h) * NBOX * DKD;
        float4 bLo = *(const float4*)&bb[h * DKD + 8 * tc];
        float4 bHi = *(const float4*)&bb[h * DKD + 8 * tc + 4];
#pragma unroll
        for (int i = 0; i < 2; ++i) {
            int row = m0 + r0 + i;
            float2 c0 = unpack2(acc[i][0]);
            float2 c1 = unpack2(acc[i][1]);
            float2 c2 = unpack2(acc[i][2]);
            float2 c3 = unpack2(acc[i][3]);
            *(float4*)&outp[row * DKD + 8 * tc] =
                make_float4(c0.x + bLo.x, c0.y + bLo.y, c1.x + bLo.z, c1.y + bLo.w);
            *(float4*)&outp[row * DKD + 8 * tc + 4] =
                make_float4(c2.x + bHi.x, c2.y + bHi.y, c3.x + bHi.z, c3.y + bHi.w);
        }
    } else {
        // ---------------- gate path ----------------
        float (*pos_s)[65] = (float(*)[65])smem_raw;             // 64x65 = 16640 B
        float* wg_s = (float*)(smem_raw + 64 * 65 * 4);          // 16x64 =  4096 B

        int p0 = (blockIdx.x - 192) * 64;   // pair base (pair = m*128+n)

        ((float4*)wg_s)[tid] = ((const float4*)WG)[tid];
#pragma unroll
        for (int it = 0; it < 4; ++it) {
            int fidx = tid + 256 * it;
            int pl = fidx >> 4, g4 = fidx & 15;
            float4 v = ((const float4*)pos)[(long)(p0 + pl) * 16 + g4];
            pos_s[pl][4 * g4 + 0] = v.x;
            pos_s[pl][4 * g4 + 1] = v.y;
            pos_s[pl][4 * g4 + 2] = v.z;
            pos_s[pl][4 * g4 + 3] = v.w;
        }
        __syncthreads();

        int row = tid & 63;
        int hg  = tid >> 6;       // heads {hg, hg+4, hg+8, hg+12}
        float acc[4] = {0.f, 0.f, 0.f, 0.f};
#pragma unroll
        for (int g = 0; g < DG; ++g) {
            float pv = pos_s[row][g];
#pragma unroll
            for (int j = 0; j < 4; ++j)
                acc[j] = fmaf(pv, wg_s[(hg + 4 * j) * DG + g], acc[j]);
        }
#pragma unroll
        for (int j = 0; j < 4; ++j) {
            int h = hg + 4 * j;
            float x = acc[j] + bg[h];
            g_glog[h * (NBOX * NBOX) + p0 + row] = __logf(fmaxf(x, 1e-6f));
        }
    }
}

// ---------------------------------------------------------------------------
// k_attn: 32x128 score tile (f32x2 FMA), + glog, row softmax, partial colsums.
// grid (4, 16), 256 threads. Thread = rows 4rg..4rg+3 x cols 4cg..4cg+3.
// ---------------------------------------------------------------------------
__global__ void k_attn() {
    __shared__ __align__(16) ull As2[32][33];
    __shared__ __align__(16) float Bs[32][132];
    __shared__ float psum[8][128];

    int tid = threadIdx.x;
    int mt = blockIdx.x, h = blockIdx.y;
    int m0 = mt * 32;
    int rg = tid >> 5;
    int cg = tid & 31;

    const float* kmat = g_qkv + (long)(0 * H + h) * NBOX * DKD;
    const float* qmat = g_qkv + (long)(1 * H + h) * NBOX * DKD;

    ull acc[4][2] = {};

    for (int kk = 0; kk < DKD; kk += 32) {
        {
            int r = tid >> 3, c4 = tid & 7;
            float4 v = *(const float4*)&kmat[(m0 + r) * DKD + kk + 4 * c4];
            As2[r][4 * c4 + 0] = dup2(v.x);
            As2[r][4 * c4 + 1] = dup2(v.y);
            As2[r][4 * c4 + 2] = dup2(v.z);
            As2[r][4 * c4 + 3] = dup2(v.w);
        }
#pragma unroll
        for (int it = 0; it < 4; ++it) {
            int fidx = tid + 256 * it;
            int n = fidx >> 3, c4 = fidx & 7;
            float4 v = *(const float4*)&qmat[n * DKD + kk + 4 * c4];
            Bs[4 * c4 + 0][n] = v.x;
            Bs[4 * c4 + 1][n] = v.y;
            Bs[4 * c4 + 2][n] = v.z;
            Bs[4 * c4 + 3][n] = v.w;
        }
        __syncthreads();

#pragma unroll
        for (int d = 0; d < 32; ++d) {
            ulonglong2 b = *(ulonglong2*)&Bs[d][4 * cg];
#pragma unroll
            for (int i = 0; i < 4; ++i) {
                ull a = As2[4 * rg + i][d];
                fma2(acc[i][0], a, b.x);
                fma2(acc[i][1], a, b.y);
            }
        }
        __syncthreads();
    }

    const float scale = 0.08838834764831843f;  // 1/sqrt(128)
    float csum[4] = {0.f, 0.f, 0.f, 0.f};
#pragma unroll
    for (int i = 0; i < 4; ++i) {
        int m = m0 + 4 * rg + i;
        float4 gl = *(const float4*)&g_glog[((long)h * NBOX + m) * NBOX + 4 * cg];
        float2 s0 = unpack2(acc[i][0]);
        float2 s1 = unpack2(acc[i][1]);
        float l[4];
        l[0] = s0.x * scale + gl.x;
        l[1] = s0.y * scale + gl.y;
        l[2] = s1.x * scale + gl.z;
        l[3] = s1.y * scale + gl.w;

        float mx = fmaxf(fmaxf(l[0], l[1]), fmaxf(l[2], l[3]));
#pragma unroll
        for (int off = 16; off; off >>= 1)
            mx = fmaxf(mx, __shfl_xor_sync(0xffffffffu, mx, off));

        float e[4], s = 0.f;
#pragma unroll
        for (int j = 0; j < 4; ++j) { e[j] = __expf(l[j] - mx); s += e[j]; }
#pragma unroll
        for (int off = 16; off; off >>= 1)
            s += __shfl_xor_sync(0xffffffffu, s, off);

        float rinv = 1.0f / s;
#pragma unroll
        for (int j = 0; j < 4; ++j) csum[j] += e[j] * rinv;
    }

#pragma unroll
    for (int j = 0; j < 4; ++j) psum[rg][4 * cg + j] = csum[j];
    __syncthreads();

    if (tid < 128) {
        float s = 0.f;
#pragma unroll
        for (int ww = 0; ww < 8; ++ww) s += psum[ww][tid];
        g_partial[(h * 4 + mt) * DKD + tid] = s;
    }
}

// ---------------------------------------------------------------------------
// k_out: out[i, c, d] = v[h,i,k]*colsum[h,k] + f_a[i,d]   (c = h*128+k)
// colsum computed inline from 4 partials. 16.7M float4 streaming stores.
// ---------------------------------------------------------------------------
__global__ void k_out(const float* __restrict__ f_a, float4* __restrict__ out) {
    int idx = blockIdx.x * 512 + threadIdx.x;   // 0..2^24-1
    int d4 = idx & 63;
    int c  = (idx >> 6) & 2047;
    int i  = idx >> 17;
    int h  = c >> 7;
    int k  = c & 127;

    float cs = g_partial[(h * 4 + 0) * DKD + k]
             + g_partial[(h * 4 + 1) * DKD + k]
             + g_partial[(h * 4 + 2) * DKD + k]
             + g_partial[(h * 4 + 3) * DKD + k];
    float s = g_qkv[((long)(2 * H + h) * NBOX + i) * DKD + k] * cs;
    float4 f = ((const float4*)f_a)[i * 64 + d4];
    __stcs(&out[idx], make_float4(s + f.x, s + f.y, s + f.z, s + f.w));
}

// ---------------------------------------------------------------------------
extern "C" void kernel_launch(void* const* d_in, const int* in_sizes, int n_in,
                              void* d_out, int out_size) {
    const float* f_a = (const float*)d_in[0];
    const float* pos = (const float*)d_in[1];
    const float* WG  = (const float*)d_in[2];
    const float* bg  = (const float*)d_in[3];
    const float* WK  = (const float*)d_in[4];
    const float* bk  = (const float*)d_in[5];
    const float* WQ  = (const float*)d_in[6];
    const float* bq  = (const float*)d_in[7];
    const float* WV  = (const float*)d_in[8];
    const float* bv  = (const float*)d_in[9];

    k_front<<<448, 256>>>(f_a, pos, WG, bg, WK, bk, WQ, bq, WV, bv);
    k_attn<<<dim3(4, 16), 256>>>();
    k_out<<<32768, 512>>>(f_a, (float4*)d_out);
}